// round 7
// baseline (speedup 1.0000x reference)
#include <cuda_runtime.h>
#include <cuda_bf16.h>

#define Bn 16
#define Sn 512
#define Tn 16
#define Pn 4
#define Gn 128                 // Sn / Pn
#define NPATCH (Bn * Gn * Gn)  // 262144

// Intermediate normalized CAM, layout [b, gy, gx, t] (t contiguous) — 16 MB scratch.
__device__ float g_top[(size_t)NPATCH * Tn];

// ---------------------------------------------------------------------------
// Kernel 1: per-patch c[t] = sum_k input[b, gy*4+py, gx*4+px, t] * W[n, k, 0]
// then (c - min_t) / (max_t - min_t).
// 4 threads per patch; each thread owns a t-quad (float4) -> 16 LDG.128/thread
// instead of 16 LDG.32 (4x fewer load instructions for the same bytes).
// ---------------------------------------------------------------------------
__global__ void __launch_bounds__(256)
patch_cam_kernel(const float* __restrict__ input, const float* __restrict__ w3)
{
    int tid = blockIdx.x * blockDim.x + threadIdx.x;
    int sub = tid & 3;                // t-quad index (t = 4*sub .. 4*sub+3)
    int n = tid >> 2;                 // patch index: ((b*G)+gy)*G + gx
    int gx = n & (Gn - 1);
    int gy = (n >> 7) & (Gn - 1);
    int b  = n >> 14;

    int lane = threadIdx.x & 31;

    // Lane g of each quad loads W[n, k=4g+j, 0] for j=0..3 (stride 6 floats).
    const float* wbase = &w3[(size_t)n * (Pn * Pn * 6) + sub * 4 * 6];
    float wv0 = __ldg(wbase);
    float wv1 = __ldg(wbase + 6);
    float wv2 = __ldg(wbase + 12);
    float wv3 = __ldg(wbase + 18);

    const float4* base =
        (const float4*)(input + (((size_t)b * Sn + gy * Pn) * Sn + gx * Pn) * Tn) + sub;

    float4 acc = make_float4(0.f, 0.f, 0.f, 0.f);
    int qb = lane & ~3;               // base lane of this quad

    #pragma unroll
    for (int k = 0; k < 16; ++k) {
        float wk;
        {
            int src = qb | (k >> 2);
            switch (k & 3) {
                case 0: wk = __shfl_sync(0xffffffffu, wv0, src); break;
                case 1: wk = __shfl_sync(0xffffffffu, wv1, src); break;
                case 2: wk = __shfl_sync(0xffffffffu, wv2, src); break;
                default: wk = __shfl_sync(0xffffffffu, wv3, src); break;
            }
        }
        int py = k >> 2;
        int px = k & 3;
        float4 p = base[((size_t)py * Sn + px) * (Tn / 4)];
        acc.x = fmaf(p.x, wk, acc.x);
        acc.y = fmaf(p.y, wk, acc.y);
        acc.z = fmaf(p.z, wk, acc.z);
        acc.w = fmaf(p.w, wk, acc.w);
    }

    // min/max over 16 t: 4 in-thread + across the 4 lanes of the quad.
    float mn = fminf(fminf(acc.x, acc.y), fminf(acc.z, acc.w));
    float mx = fmaxf(fmaxf(acc.x, acc.y), fmaxf(acc.z, acc.w));
    #pragma unroll
    for (int o = 1; o <= 2; o <<= 1) {
        mn = fminf(mn, __shfl_xor_sync(0xffffffffu, mn, o));
        mx = fmaxf(mx, __shfl_xor_sync(0xffffffffu, mx, o));
    }

    float inv = 1.0f / (mx - mn);
    float4 v;
    v.x = (acc.x - mn) * inv;
    v.y = (acc.y - mn) * inv;
    v.z = (acc.z - mn) * inv;
    v.w = (acc.w - mn) * inv;
    ((float4*)&g_top[(size_t)n * Tn])[sub] = v;
}

// ---------------------------------------------------------------------------
// Kernel 2: bilinear upsample (g,g)->(s,s), align_corners=True.
// Block = (b, 4 output rows) x full width 512.
// Stage 1: y-pre-blend needed g_top rows into smem [4][128][16]
//          (padded to 20 floats/col), unrolled for MLP.
// Stage 2: float4-linear mapping over the output tile: fully coalesced STG.
// ---------------------------------------------------------------------------
#define COLPAD 20   // floats per padded column (80 B, 16B-aligned)

__global__ void __launch_bounds__(256)
upsample_kernel(float* __restrict__ out)
{
    __shared__ float s[4 * Gn * COLPAD];     // 40960 B: y-blended rows

    int blk = blockIdx.x;
    int yt = blk & (Gn - 1);                 // y-tile (4 rows each)
    int b  = blk >> 7;
    int y0 = yt << 2;

    const float r = 127.0f / 511.0f;

    // Stage 1: 4 rows x 128 cols x 4 float4 = 2048 items, 8 per thread (unrolled).
    #pragma unroll
    for (int it = 0; it < 8; ++it) {
        int i = threadIdx.x + (it << 8);
        int row = i >> 9;                    // 0..3 local y
        int rem = i & 511;
        int col = rem >> 2;
        int q   = rem & 3;

        int y = y0 + row;
        float cy = (float)y * r;
        int i0 = min((int)cy, Gn - 2);
        float wy = cy - (float)i0;

        const float4* g0 = (const float4*)&g_top[(((size_t)(b * Gn + i0))     * Gn + col) * Tn];
        const float4* g1 = (const float4*)&g_top[(((size_t)(b * Gn + i0 + 1)) * Gn + col) * Tn];
        float4 a = g0[q], c = g1[q];
        float4 v;
        v.x = a.x + wy * (c.x - a.x);
        v.y = a.y + wy * (c.y - a.y);
        v.z = a.z + wy * (c.z - a.z);
        v.w = a.w + wy * (c.w - a.w);
        *(float4*)&s[(row * Gn + col) * COLPAD + q * 4] = v;
    }
    __syncthreads();

    // Stage 2: block tile = 4 rows x 512 px x 4 quarters = 8192 float4.
    float4* o4 = (float4*)(out + ((size_t)(b * Sn + y0)) * Sn * Tn);

    #pragma unroll 8
    for (int it = 0; it < 32; ++it) {
        int f = threadIdx.x + (it << 8);     // 0..8191
        int q   = f & 3;
        int x   = (f >> 2) & (Sn - 1);
        int row = f >> 11;

        float cx = (float)x * r;
        int j0 = min((int)cx, Gn - 2);
        float wx = cx - (float)j0;

        const float* sp = &s[(row * Gn + j0) * COLPAD + q * 4];
        float4 a  = *(const float4*)sp;
        float4 bb = *(const float4*)(sp + COLPAD);
        float4 v;
        v.x = a.x + wx * (bb.x - a.x);
        v.y = a.y + wx * (bb.y - a.y);
        v.z = a.z + wx * (bb.z - a.z);
        v.w = a.w + wx * (bb.w - a.w);
        o4[f] = v;
    }
}

extern "C" void kernel_launch(void* const* d_in, const int* in_sizes, int n_in,
                              void* d_out, int out_size)
{
    const float* input = (const float*)d_in[0];   // (16,512,512,16) f32
    const float* w3    = (const float*)d_in[1];   // (262144,16,6)  f32
    float* out = (float*)d_out;                   // (16*512*512, 16) f32

    // Kernel 1: NPATCH * 4 threads (4 threads per patch)
    {
        int total = NPATCH * 4;                   // 1,048,576
        patch_cam_kernel<<<total / 256, 256>>>(input, w3);
    }
    // Kernel 2: 16 b x 128 y-tiles
    {
        upsample_kernel<<<Bn * Gn, 256>>>(out);
    }
    (void)in_sizes; (void)n_in; (void)out_size;
}

// round 8
// speedup vs baseline: 1.0713x; 1.0713x over previous
#include <cuda_runtime.h>
#include <cuda_bf16.h>

#define Bn 16
#define Sn 512
#define Tn 16
#define Pn 4
#define Gn 128                 // Sn / Pn
#define NPATCH (Bn * Gn * Gn)  // 262144

// Intermediate normalized CAM, layout [b, gy, gx, t] (t contiguous) — 16 MB scratch.
__device__ float g_top[(size_t)NPATCH * Tn];

// ---------------------------------------------------------------------------
// Kernel 1: per-patch c[t] = sum_k input[b, gy*4+py, gx*4+px, t] * W[n, k, 0]
// then (c - min_t) / (max_t - min_t). 16 threads per patch (one per t).
// (R6 mapping: best per-instruction coalescing — 16 contiguous lanes/pixel.)
// ---------------------------------------------------------------------------
__global__ void __launch_bounds__(256)
patch_cam_kernel(const float* __restrict__ input, const float* __restrict__ w3)
{
    int tid = blockIdx.x * blockDim.x + threadIdx.x;
    int t = tid & 15;
    int n = tid >> 4;                 // patch index: ((b*G)+gy)*G + gx
    int gx = n & (Gn - 1);
    int gy = (n >> 7) & (Gn - 1);
    int b  = n >> 14;

    // Thread t loads W[n, k=t, m=0] (stride 6 floats); broadcast via shfl below.
    float w = __ldcs(&w3[(size_t)n * (Pn * Pn * 6) + t * 6]);

    const float* base = input + (((size_t)b * Sn + gy * Pn) * Sn + gx * Pn) * Tn + t;

    int lane = threadIdx.x & 31;
    unsigned grp = (unsigned)(lane & 16);   // which 16-lane half of the warp

    float acc = 0.0f;
    #pragma unroll
    for (int k = 0; k < 16; ++k) {
        float wk = __shfl_sync(0xffffffffu, w, (int)(grp | (unsigned)k));
        int py = k >> 2;
        int px = k & 3;
        acc = fmaf(__ldcs(&base[((size_t)py * Sn + px) * Tn]), wk, acc);
    }

    // min / max over the 16 t-lanes of this patch (xor 8,4,2,1 stays in-group)
    float mn = acc, mx = acc;
    #pragma unroll
    for (int o = 8; o >= 1; o >>= 1) {
        mn = fminf(mn, __shfl_xor_sync(0xffffffffu, mn, o));
        mx = fmaxf(mx, __shfl_xor_sync(0xffffffffu, mx, o));
    }

    g_top[(size_t)n * Tn + t] = (acc - mn) / (mx - mn);
}

// ---------------------------------------------------------------------------
// Kernel 2: bilinear upsample (g,g)->(s,s), align_corners=True.
// Block = (b, 4 output rows) x full width 512.
// Stage 1: y-pre-blend needed g_top rows into smem [4][128][16]
//          (padded to 20 floats/col), unrolled for MLP.
// Stage 2: float4-linear mapping over the output tile: fully coalesced STG,
//          streamed (__stcs) so the dead output lines don't evict g_top.
// __launch_bounds__(256,5): 5 blocks/SM (smem-limited), occ 62.5% cap.
// ---------------------------------------------------------------------------
#define COLPAD 20   // floats per padded column (80 B, 16B-aligned)

__global__ void __launch_bounds__(256, 5)
upsample_kernel(float* __restrict__ out)
{
    __shared__ float s[4 * Gn * COLPAD];     // 40960 B: y-blended rows

    int blk = blockIdx.x;
    int yt = blk & (Gn - 1);                 // y-tile (4 rows each)
    int b  = blk >> 7;
    int y0 = yt << 2;

    const float r = 127.0f / 511.0f;

    // Stage 1: 4 rows x 128 cols x 4 float4 = 2048 items, 8 per thread (unrolled).
    #pragma unroll
    for (int it = 0; it < 8; ++it) {
        int i = threadIdx.x + (it << 8);
        int row = i >> 9;                    // 0..3 local y
        int rem = i & 511;
        int col = rem >> 2;
        int q   = rem & 3;

        int y = y0 + row;
        float cy = (float)y * r;
        int i0 = min((int)cy, Gn - 2);
        float wy = cy - (float)i0;

        const float4* g0 = (const float4*)&g_top[(((size_t)(b * Gn + i0))     * Gn + col) * Tn];
        const float4* g1 = (const float4*)&g_top[(((size_t)(b * Gn + i0 + 1)) * Gn + col) * Tn];
        float4 a = g0[q], c = g1[q];
        float4 v;
        v.x = a.x + wy * (c.x - a.x);
        v.y = a.y + wy * (c.y - a.y);
        v.z = a.z + wy * (c.z - a.z);
        v.w = a.w + wy * (c.w - a.w);
        *(float4*)&s[(row * Gn + col) * COLPAD + q * 4] = v;
    }
    __syncthreads();

    // Stage 2: block tile = 4 rows x 512 px x 4 quarters = 8192 float4.
    float4* o4 = (float4*)(out + ((size_t)(b * Sn + y0)) * Sn * Tn);

    #pragma unroll 8
    for (int it = 0; it < 32; ++it) {
        int f = threadIdx.x + (it << 8);     // 0..8191
        int q   = f & 3;
        int x   = (f >> 2) & (Sn - 1);
        int row = f >> 11;

        float cx = (float)x * r;
        int j0 = min((int)cx, Gn - 2);
        float wx = cx - (float)j0;

        const float* sp = &s[(row * Gn + j0) * COLPAD + q * 4];
        float4 a  = *(const float4*)sp;
        float4 bb = *(const float4*)(sp + COLPAD);
        float4 v;
        v.x = a.x + wx * (bb.x - a.x);
        v.y = a.y + wx * (bb.y - a.y);
        v.z = a.z + wx * (bb.z - a.z);
        v.w = a.w + wx * (bb.w - a.w);
        __stcs(&o4[f], v);
    }
}

extern "C" void kernel_launch(void* const* d_in, const int* in_sizes, int n_in,
                              void* d_out, int out_size)
{
    const float* input = (const float*)d_in[0];   // (16,512,512,16) f32
    const float* w3    = (const float*)d_in[1];   // (262144,16,6)  f32
    float* out = (float*)d_out;                   // (16*512*512, 16) f32

    // Kernel 1: NPATCH * 16 threads (16 threads per patch)
    {
        int total = NPATCH * Tn;                  // 4,194,304
        patch_cam_kernel<<<total / 256, 256>>>(input, w3);
    }
    // Kernel 2: 16 b x 128 y-tiles
    {
        upsample_kernel<<<Bn * Gn, 256>>>(out);
    }
    (void)in_sizes; (void)n_in; (void)out_size;
}

// round 9
// speedup vs baseline: 1.1175x; 1.0432x over previous
#include <cuda_runtime.h>
#include <cuda_bf16.h>

#define Bn 16
#define Sn 512
#define Tn 16
#define Pn 4
#define Gn 128                 // Sn / Pn
#define NPATCH (Bn * Gn * Gn)  // 262144

// Intermediate normalized CAM, layout [b, gy, gx, t] (t contiguous) — 16 MB scratch.
__device__ float g_top[(size_t)NPATCH * Tn];

// ---------------------------------------------------------------------------
// Kernel 1: per-patch c[t] = sum_k input[b, gy*4+py, gx*4+px, t] * W[n, k, 0]
// then (c - min_t) / (max_t - min_t). 16 threads per patch (one per t).
// Streaming loads (__ldcs): input and W are read-once, keep L2 for g_top.
// ---------------------------------------------------------------------------
__global__ void __launch_bounds__(256)
patch_cam_kernel(const float* __restrict__ input, const float* __restrict__ w3)
{
    int tid = blockIdx.x * blockDim.x + threadIdx.x;
    int t = tid & 15;
    int n = tid >> 4;                 // patch index: ((b*G)+gy)*G + gx
    int gx = n & (Gn - 1);
    int gy = (n >> 7) & (Gn - 1);
    int b  = n >> 14;

    // Thread t loads W[n, k=t, m=0] (stride 6 floats); broadcast via shfl below.
    float w = __ldcs(&w3[(size_t)n * (Pn * Pn * 6) + t * 6]);

    const float* base = input + (((size_t)b * Sn + gy * Pn) * Sn + gx * Pn) * Tn + t;

    int lane = threadIdx.x & 31;
    unsigned grp = (unsigned)(lane & 16);   // which 16-lane half of the warp

    float acc = 0.0f;
    #pragma unroll
    for (int k = 0; k < 16; ++k) {
        float wk = __shfl_sync(0xffffffffu, w, (int)(grp | (unsigned)k));
        int py = k >> 2;
        int px = k & 3;
        acc = fmaf(__ldcs(&base[((size_t)py * Sn + px) * Tn]), wk, acc);
    }

    // min / max over the 16 t-lanes of this patch (xor 8,4,2,1 stays in-group)
    float mn = acc, mx = acc;
    #pragma unroll
    for (int o = 8; o >= 1; o >>= 1) {
        mn = fminf(mn, __shfl_xor_sync(0xffffffffu, mn, o));
        mx = fmaxf(mx, __shfl_xor_sync(0xffffffffu, mx, o));
    }

    g_top[(size_t)n * Tn + t] = (acc - mn) / (mx - mn);
}

// ---------------------------------------------------------------------------
// Kernel 2: bilinear upsample (g,g)->(s,s), align_corners=True.
// Exact R6 configuration (best measured): block = (b, 4 rows) x 512 width,
// y-pre-blend into padded smem, float4-linear stage 2, plain stores,
// no launch-bounds cap (regs 54, 4 blocks/SM).
// ---------------------------------------------------------------------------
#define COLPAD 20   // floats per padded column (80 B, 16B-aligned)

__global__ void __launch_bounds__(256)
upsample_kernel(float* __restrict__ out)
{
    __shared__ float s[4 * Gn * COLPAD];     // 40960 B: y-blended rows

    int blk = blockIdx.x;
    int yt = blk & (Gn - 1);                 // y-tile (4 rows each)
    int b  = blk >> 7;
    int y0 = yt << 2;

    const float r = 127.0f / 511.0f;

    // Stage 1: 4 rows x 128 cols x 4 float4 = 2048 items, 8 per thread (unrolled).
    #pragma unroll
    for (int it = 0; it < 8; ++it) {
        int i = threadIdx.x + (it << 8);
        int row = i >> 9;                    // 0..3 local y
        int rem = i & 511;
        int col = rem >> 2;
        int q   = rem & 3;

        int y = y0 + row;
        float cy = (float)y * r;
        int i0 = min((int)cy, Gn - 2);
        float wy = cy - (float)i0;

        const float4* g0 = (const float4*)&g_top[(((size_t)(b * Gn + i0))     * Gn + col) * Tn];
        const float4* g1 = (const float4*)&g_top[(((size_t)(b * Gn + i0 + 1)) * Gn + col) * Tn];
        float4 a = g0[q], c = g1[q];
        float4 v;
        v.x = a.x + wy * (c.x - a.x);
        v.y = a.y + wy * (c.y - a.y);
        v.z = a.z + wy * (c.z - a.z);
        v.w = a.w + wy * (c.w - a.w);
        *(float4*)&s[(row * Gn + col) * COLPAD + q * 4] = v;
    }
    __syncthreads();

    // Stage 2: block tile = 4 rows x 512 px x 4 quarters = 8192 float4.
    float4* o4 = (float4*)(out + ((size_t)(b * Sn + y0)) * Sn * Tn);

    #pragma unroll 8
    for (int it = 0; it < 32; ++it) {
        int f = threadIdx.x + (it << 8);     // 0..8191
        int q   = f & 3;
        int x   = (f >> 2) & (Sn - 1);
        int row = f >> 11;

        float cx = (float)x * r;
        int j0 = min((int)cx, Gn - 2);
        float wx = cx - (float)j0;

        const float* sp = &s[(row * Gn + j0) * COLPAD + q * 4];
        float4 a  = *(const float4*)sp;
        float4 bb = *(const float4*)(sp + COLPAD);
        float4 v;
        v.x = a.x + wx * (bb.x - a.x);
        v.y = a.y + wx * (bb.y - a.y);
        v.z = a.z + wx * (bb.z - a.z);
        v.w = a.w + wx * (bb.w - a.w);
        o4[f] = v;
    }
}

extern "C" void kernel_launch(void* const* d_in, const int* in_sizes, int n_in,
                              void* d_out, int out_size)
{
    const float* input = (const float*)d_in[0];   // (16,512,512,16) f32
    const float* w3    = (const float*)d_in[1];   // (262144,16,6)  f32
    float* out = (float*)d_out;                   // (16*512*512, 16) f32

    // Kernel 1: NPATCH * 16 threads (16 threads per patch)
    {
        int total = NPATCH * Tn;                  // 4,194,304
        patch_cam_kernel<<<total / 256, 256>>>(input, w3);
    }
    // Kernel 2: 16 b x 128 y-tiles
    {
        upsample_kernel<<<Bn * Gn, 256>>>(out);
    }
    (void)in_sizes; (void)n_in; (void)out_size;
}